// round 1
// baseline (speedup 1.0000x reference)
#include <cuda_runtime.h>
#include <cuda_bf16.h>

#define N_DIM 2048
#define BATCH 8192

// Scratch: allocation is banned, use __device__ globals (16 MB each).
__device__ float g_S[N_DIM * N_DIM];
__device__ float g_T[N_DIM * N_DIM];
__device__ float g_T2[N_DIM * N_DIM];
__device__ float g_Q[N_DIM * N_DIM];

// Build antisymmetric S from strict-upper-triangle flat vector.
// Also initialize T = S and Q = I + S in the same pass.
__global__ void build_S_kernel(const float* __restrict__ S_flat) {
    int idx = blockIdx.x * blockDim.x + threadIdx.x;
    if (idx >= N_DIM * N_DIM) return;
    int i = idx / N_DIM;
    int j = idx % N_DIM;
    float v = 0.0f;
    if (i < j) {
        int f = i * (2 * N_DIM - i - 1) / 2 + (j - i - 1);
        v = S_flat[f];
    } else if (i > j) {
        int f = j * (2 * N_DIM - j - 1) / 2 + (i - j - 1);
        v = -S_flat[f];
    }
    g_S[idx] = v;
    g_T[idx] = v;
    g_Q[idx] = v + (i == j ? 1.0f : 0.0f);
}

// Tiled SGEMM: C = alpha * (A @ B); optionally Qacc += alpha * (A @ B).
// A: M x K row-major, B: K x N row-major. M,N multiples of 128; K multiple of 8.
#define BM 128
#define BN 128
#define BK 8
#define TM 8
#define TN 8

__global__ __launch_bounds__(256) void sgemm_kernel(
    const float* __restrict__ A, const float* __restrict__ B,
    float* __restrict__ C, float* __restrict__ Qacc,
    float alpha, int M, int N, int K)
{
    __shared__ float As[BK][BM];
    __shared__ float Bs[BK][BN];

    const int tid = threadIdx.x;
    const int rowBase = blockIdx.y * BM;
    const int colBase = blockIdx.x * BN;

    // compute-thread micro-tile origin
    const int crow = (tid / (BN / TN)) * TM;  // 0..120 step 8
    const int ccol = (tid % (BN / TN)) * TN;  // 0..120 step 8

    // load mapping: A tile 128x8 (one float4/thread), B tile 8x128 (one float4/thread)
    const int aRow = tid >> 1;          // 0..127
    const int aCol = (tid & 1) << 2;    // 0 or 4
    const int bRow = tid >> 5;          // 0..7
    const int bCol = (tid & 31) << 2;   // 0..124 step 4

    const float* Aptr = A + (size_t)(rowBase + aRow) * K + aCol;
    const float* Bptr = B + (size_t)bRow * N + colBase + bCol;

    float acc[TM][TN] = {};
    float regM[TM], regN[TN];

    for (int k0 = 0; k0 < K; k0 += BK) {
        float4 av = *reinterpret_cast<const float4*>(Aptr);
        As[aCol + 0][aRow] = av.x;
        As[aCol + 1][aRow] = av.y;
        As[aCol + 2][aRow] = av.z;
        As[aCol + 3][aRow] = av.w;
        *reinterpret_cast<float4*>(&Bs[bRow][bCol]) =
            *reinterpret_cast<const float4*>(Bptr);
        __syncthreads();
        Aptr += BK;
        Bptr += (size_t)BK * N;

#pragma unroll
        for (int k = 0; k < BK; ++k) {
#pragma unroll
            for (int i = 0; i < TM; ++i) regM[i] = As[k][crow + i];
#pragma unroll
            for (int j = 0; j < TN; ++j) regN[j] = Bs[k][ccol + j];
#pragma unroll
            for (int i = 0; i < TM; ++i)
#pragma unroll
                for (int j = 0; j < TN; ++j)
                    acc[i][j] += regM[i] * regN[j];
        }
        __syncthreads();
    }

    // epilogue: scale, store C, optionally accumulate into Qacc
#pragma unroll
    for (int i = 0; i < TM; ++i) {
#pragma unroll
        for (int j = 0; j < TN; j += 4) {
            size_t idx = (size_t)(rowBase + crow + i) * N + (colBase + ccol + j);
            float4 v;
            v.x = acc[i][j + 0] * alpha;
            v.y = acc[i][j + 1] * alpha;
            v.z = acc[i][j + 2] * alpha;
            v.w = acc[i][j + 3] * alpha;
            *reinterpret_cast<float4*>(C + idx) = v;
            if (Qacc != nullptr) {
                float4 q = *reinterpret_cast<float4*>(Qacc + idx);
                q.x += v.x; q.y += v.y; q.z += v.z; q.w += v.w;
                *reinterpret_cast<float4*>(Qacc + idx) = q;
            }
        }
    }
}

extern "C" void kernel_launch(void* const* d_in, const int* in_sizes, int n_in,
                              void* d_out, int out_size) {
    const float* X      = (const float*)d_in[0];   // [BATCH, N]
    const float* S_flat = (const float*)d_in[1];   // [N*(N-1)/2]
    float* Y = (float*)d_out;                      // [BATCH, N]

    float *S, *T, *T2, *Q;
    cudaGetSymbolAddress((void**)&S,  g_S);
    cudaGetSymbolAddress((void**)&T,  g_T);
    cudaGetSymbolAddress((void**)&T2, g_T2);
    cudaGetSymbolAddress((void**)&Q,  g_Q);

    // 1) Build S, T=S, Q=I+S
    {
        int total = N_DIM * N_DIM;
        build_S_kernel<<<(total + 255) / 256, 256>>>(S_flat);
    }

    // 2) Taylor terms: for i=2..9:  Tnew = (T @ S) / i;  Q += Tnew
    {
        dim3 grid(N_DIM / BN, N_DIM / BM);
        float* Tin = T;
        float* Tout = T2;
        for (int i = 2; i <= 9; ++i) {
            sgemm_kernel<<<grid, 256>>>(Tin, S, Tout, Q, 1.0f / (float)i,
                                        N_DIM, N_DIM, N_DIM);
            float* tmp = Tin; Tin = Tout; Tout = tmp;
        }
    }

    // 3) Y = X @ Q
    {
        dim3 grid(N_DIM / BN, BATCH / BM);
        sgemm_kernel<<<grid, 256>>>(X, Q, Y, nullptr, 1.0f,
                                    BATCH, N_DIM, N_DIM);
    }
}

// round 2
// speedup vs baseline: 1.5977x; 1.5977x over previous
#include <cuda_runtime.h>
#include <cuda_bf16.h>
#include <cuda_pipeline.h>
#include <mma.h>

using namespace nvcuda;

#define N_DIM 2048
#define BATCH 8192

// Scratch: allocation is banned, use __device__ globals (16 MB each).
__device__ float g_S[N_DIM * N_DIM];
__device__ float g_T[N_DIM * N_DIM];
__device__ float g_T2[N_DIM * N_DIM];
__device__ float g_Q[N_DIM * N_DIM];

// Build antisymmetric S from strict-upper-triangle flat vector.
// Also initialize T = S and Q = I + S in the same pass.
__global__ void build_S_kernel(const float* __restrict__ S_flat) {
    int idx = blockIdx.x * blockDim.x + threadIdx.x;
    if (idx >= N_DIM * N_DIM) return;
    int i = idx / N_DIM;
    int j = idx % N_DIM;
    float v = 0.0f;
    if (i < j) {
        int f = i * (2 * N_DIM - i - 1) / 2 + (j - i - 1);
        v = S_flat[f];
    } else if (i > j) {
        int f = j * (2 * N_DIM - j - 1) / 2 + (i - j - 1);
        v = -S_flat[f];
    }
    g_S[idx] = v;
    g_T[idx] = v;
    g_Q[idx] = v + (i == j ? 1.0f : 0.0f);
}

// ---------------------------------------------------------------------------
// TF32 wmma GEMM: C = alpha * (A @ B); optionally Qacc += alpha * (A @ B).
// A: M x K row-major fp32, B: K x N row-major fp32.
// M, N multiples of 128; K multiple of 16.
// ---------------------------------------------------------------------------
#define BM 128
#define BN 128
#define BK 16
#define A_LD (BK + 8)   // 24 floats, padded to dodge bank conflicts
#define B_LD (BN + 8)   // 136 floats

__global__ __launch_bounds__(256) void tf32_gemm_kernel(
    const float* __restrict__ A, const float* __restrict__ B,
    float* __restrict__ C, float* __restrict__ Qacc,
    float alpha, int M, int N, int K)
{
    __shared__ float As[2][BM][A_LD];
    __shared__ float Bs[2][BK][B_LD];

    const int tid = threadIdx.x;
    const int warpId = tid >> 5;

    const int rowBase = blockIdx.y * BM;
    const int colBase = blockIdx.x * BN;

    // warp tile: 32 (M) x 64 (N); warp grid 4 x 2
    const int warpM0 = (warpId >> 1) * 32;
    const int warpN0 = (warpId & 1) * 64;

    // global->smem load mapping (float4 granularity)
    // A tile: 128 x 16 = 512 float4; thread handles idx = tid, tid+256
    // B tile:  16 x 128 = 512 float4; same split
    const int a_idx0 = tid, a_idx1 = tid + 256;
    const int aRow0 = a_idx0 >> 2, aCol0 = (a_idx0 & 3) << 2;
    const int aRow1 = a_idx1 >> 2, aCol1 = (a_idx1 & 3) << 2;
    const int bRow0 = tid >> 5,        bCol0 = (tid & 31) << 2;
    const int bRow1 = (tid + 256) >> 5, bCol1 = ((tid + 256) & 31) << 2;

    const int nsteps = K / BK;

    auto issue_stage = [&](int step, int buf) {
        int k0 = step * BK;
        __pipeline_memcpy_async(&As[buf][aRow0][aCol0],
                                A + (size_t)(rowBase + aRow0) * K + k0 + aCol0, 16);
        __pipeline_memcpy_async(&As[buf][aRow1][aCol1],
                                A + (size_t)(rowBase + aRow1) * K + k0 + aCol1, 16);
        __pipeline_memcpy_async(&Bs[buf][bRow0][bCol0],
                                B + (size_t)(k0 + bRow0) * N + colBase + bCol0, 16);
        __pipeline_memcpy_async(&Bs[buf][bRow1][bCol1],
                                B + (size_t)(k0 + bRow1) * N + colBase + bCol1, 16);
        __pipeline_commit();
    };

    wmma::fragment<wmma::accumulator, 16, 16, 8, float> acc[2][4];
#pragma unroll
    for (int i = 0; i < 2; ++i)
#pragma unroll
        for (int j = 0; j < 4; ++j)
            wmma::fill_fragment(acc[i][j], 0.0f);

    issue_stage(0, 0);

    for (int step = 0; step < nsteps; ++step) {
        const int cur = step & 1;
        const bool has_next = (step + 1) < nsteps;
        if (has_next) issue_stage(step + 1, cur ^ 1);

        if (has_next) __pipeline_wait_prior(1);
        else          __pipeline_wait_prior(0);
        __syncthreads();

#pragma unroll
        for (int kk = 0; kk < BK; kk += 8) {
            wmma::fragment<wmma::matrix_a, 16, 16, 8, wmma::precision::tf32,
                           wmma::row_major> afrag[2];
            wmma::fragment<wmma::matrix_b, 16, 16, 8, wmma::precision::tf32,
                           wmma::row_major> bfrag[4];
#pragma unroll
            for (int i = 0; i < 2; ++i) {
                wmma::load_matrix_sync(afrag[i], &As[cur][warpM0 + 16 * i][kk], A_LD);
#pragma unroll
                for (int t = 0; t < afrag[i].num_elements; ++t)
                    afrag[i].x[t] = wmma::__float_to_tf32(afrag[i].x[t]);
            }
#pragma unroll
            for (int j = 0; j < 4; ++j) {
                wmma::load_matrix_sync(bfrag[j], &Bs[cur][kk][warpN0 + 16 * j], B_LD);
#pragma unroll
                for (int t = 0; t < bfrag[j].num_elements; ++t)
                    bfrag[j].x[t] = wmma::__float_to_tf32(bfrag[j].x[t]);
            }
#pragma unroll
            for (int i = 0; i < 2; ++i)
#pragma unroll
                for (int j = 0; j < 4; ++j)
                    wmma::mma_sync(acc[i][j], afrag[i], bfrag[j], acc[i][j]);
        }
        __syncthreads();
    }

    // epilogue: scale by alpha, store C, optionally Qacc += result
#pragma unroll
    for (int i = 0; i < 2; ++i) {
#pragma unroll
        for (int j = 0; j < 4; ++j) {
#pragma unroll
            for (int t = 0; t < acc[i][j].num_elements; ++t)
                acc[i][j].x[t] *= alpha;
            size_t off = (size_t)(rowBase + warpM0 + 16 * i) * N
                       + (colBase + warpN0 + 16 * j);
            wmma::store_matrix_sync(C + off, acc[i][j], N, wmma::mem_row_major);
            if (Qacc != nullptr) {
                wmma::fragment<wmma::accumulator, 16, 16, 8, float> qfrag;
                wmma::load_matrix_sync(qfrag, Qacc + off, N, wmma::mem_row_major);
#pragma unroll
                for (int t = 0; t < qfrag.num_elements; ++t)
                    qfrag.x[t] += acc[i][j].x[t];
                wmma::store_matrix_sync(Qacc + off, qfrag, N, wmma::mem_row_major);
            }
        }
    }
}

extern "C" void kernel_launch(void* const* d_in, const int* in_sizes, int n_in,
                              void* d_out, int out_size) {
    const float* X      = (const float*)d_in[0];   // [BATCH, N]
    const float* S_flat = (const float*)d_in[1];   // [N*(N-1)/2]
    float* Y = (float*)d_out;                      // [BATCH, N]

    float *S, *T, *T2, *Q;
    cudaGetSymbolAddress((void**)&S,  g_S);
    cudaGetSymbolAddress((void**)&T,  g_T);
    cudaGetSymbolAddress((void**)&T2, g_T2);
    cudaGetSymbolAddress((void**)&Q,  g_Q);

    // 1) Build S, T=S, Q=I+S
    {
        int total = N_DIM * N_DIM;
        build_S_kernel<<<(total + 255) / 256, 256>>>(S_flat);
    }

    // 2) Taylor terms: for i=2..9:  Tnew = (T @ S) / i;  Q += Tnew
    {
        dim3 grid(N_DIM / BN, N_DIM / BM);
        float* Tin = T;
        float* Tout = T2;
        for (int i = 2; i <= 9; ++i) {
            tf32_gemm_kernel<<<grid, 256>>>(Tin, S, Tout, Q, 1.0f / (float)i,
                                            N_DIM, N_DIM, N_DIM);
            float* tmp = Tin; Tin = Tout; Tout = tmp;
        }
    }

    // 3) Y = X @ Q
    {
        dim3 grid(N_DIM / BN, BATCH / BM);
        tf32_gemm_kernel<<<grid, 256>>>(X, Q, Y, nullptr, 1.0f,
                                        BATCH, N_DIM, N_DIM);
    }
}

// round 3
// speedup vs baseline: 2.1828x; 1.3662x over previous
#include <cuda_runtime.h>
#include <cuda_bf16.h>
#include <cuda_pipeline.h>
#include <mma.h>

using namespace nvcuda;

#define N_DIM 2048
#define BATCH 8192

// Scratch (allocation banned -> __device__ globals).
__device__ float g_S [N_DIM * N_DIM];
__device__ float g_S2[N_DIM * N_DIM];
__device__ float g_S3[N_DIM * N_DIM];
__device__ float g_S4[N_DIM * N_DIM];
__device__ float g_U [N_DIM * N_DIM];
__device__ float g_R [N_DIM * N_DIM];
__device__ float g_X [BATCH * N_DIM];   // tf32-rounded copy of X

// Build antisymmetric S (tf32-rounded) from strict-upper-triangle flat vector.
__global__ void build_S_kernel(const float* __restrict__ S_flat) {
    int idx = blockIdx.x * blockDim.x + threadIdx.x;
    if (idx >= N_DIM * N_DIM) return;
    int i = idx / N_DIM;
    int j = idx % N_DIM;
    float v = 0.0f;
    if (i < j) {
        int f = i * (2 * N_DIM - i - 1) / 2 + (j - i - 1);
        v = S_flat[f];
    } else if (i > j) {
        int f = j * (2 * N_DIM - j - 1) / 2 + (i - j - 1);
        v = -S_flat[f];
    }
    g_S[idx] = wmma::__float_to_tf32(v);
}

// Round X to tf32 once (so GEMM mainloop needs no conversions).
__global__ void round_X_kernel(const float* __restrict__ X) {
    int f = blockIdx.x * blockDim.x + threadIdx.x;   // float4 index
    if (f >= BATCH * N_DIM / 4) return;
    float4 v = reinterpret_cast<const float4*>(X)[f];
    v.x = wmma::__float_to_tf32(v.x);
    v.y = wmma::__float_to_tf32(v.y);
    v.z = wmma::__float_to_tf32(v.z);
    v.w = wmma::__float_to_tf32(v.w);
    reinterpret_cast<float4*>(g_X)[f] = v;
}

// ---------------------------------------------------------------------------
// TF32 wmma GEMM with fused polynomial epilogue:
//   C = round?tf32():id( alpha*(A@B) + idcoef*I + e0*E0 + e1*E1 + e2*E2 + e3*E3 )
// A: MxK, B: KxN, row-major fp32 (already tf32-rounded).
// M,N multiples of 128; K multiple of 16.
// ---------------------------------------------------------------------------
#define BM 128
#define BN 128
#define BK 16
#define A_LD 20      // 16 + 4 pad
#define B_LD 132     // 128 + 4 pad
#define STAGES 3
#define A_STG (BM * A_LD)          // 2560 floats / stage
#define B_STG (BK * B_LD)          // 2112 floats / stage
#define B_BASE (STAGES * A_STG)    // 7680
#define EPI_LD 132
#define SMEM_FLOATS 16896          // max(3*A_STG+3*B_STG=14016, 128*132=16896)
#define SMEM_BYTES (SMEM_FLOATS * 4)

__global__ __launch_bounds__(256) void tf32_gemm_kernel(
    const float* __restrict__ A, const float* __restrict__ B,
    float* __restrict__ C, int M, int N, int K,
    float alpha, float idcoef,
    const float* __restrict__ E0, float e0,
    const float* __restrict__ E1, float e1,
    const float* __restrict__ E2, float e2,
    const float* __restrict__ E3, float e3,
    int doRound)
{
    extern __shared__ float sm[];

    const int tid = threadIdx.x;
    const int warpId = tid >> 5;
    const int rowBase = blockIdx.y * BM;
    const int colBase = blockIdx.x * BN;

    // warp tile 32(M) x 64(N); warp grid 4x2
    const int warpM0 = (warpId >> 1) * 32;
    const int warpN0 = (warpId & 1) * 64;

    // load mapping (float4)
    const int aRow0 = tid >> 2,          aCol0 = (tid & 3) << 2;
    const int aRow1 = (tid + 256) >> 2,  aCol1 = (tid & 3) << 2;  // same col pattern
    const int bRow0 = tid >> 5,          bCol0 = (tid & 31) << 2;
    const int bRow1 = (tid >> 5) + 8,    bCol1 = bCol0;

    const float* aP0 = A + (size_t)(rowBase + aRow0) * K + aCol0;
    const float* aP1 = A + (size_t)(rowBase + aRow1) * K + aCol1;
    const float* bP0 = B + (size_t)bRow0 * N + colBase + bCol0;
    const float* bP1 = B + (size_t)bRow1 * N + colBase + bCol1;

    const int nsteps = K / BK;

    auto issue = [&](int step) {
        int buf = step % STAGES;
        size_t ka = (size_t)step * BK;
        float* As = sm + buf * A_STG;
        float* Bs = sm + B_BASE + buf * B_STG;
        __pipeline_memcpy_async(As + aRow0 * A_LD + aCol0, aP0 + ka, 16);
        __pipeline_memcpy_async(As + aRow1 * A_LD + aCol1, aP1 + ka, 16);
        __pipeline_memcpy_async(Bs + bRow0 * B_LD + bCol0, bP0 + ka * N, 16);
        __pipeline_memcpy_async(Bs + bRow1 * B_LD + bCol1, bP1 + ka * N, 16);
        __pipeline_commit();
    };

    wmma::fragment<wmma::accumulator, 16, 16, 8, float> acc[2][4];
#pragma unroll
    for (int i = 0; i < 2; ++i)
#pragma unroll
        for (int j = 0; j < 4; ++j)
            wmma::fill_fragment(acc[i][j], 0.0f);

    issue(0);
    issue(1);

    for (int step = 0; step < nsteps; ++step) {
        if (step + 2 < nsteps) { issue(step + 2); __pipeline_wait_prior(2); }
        else if (step + 1 < nsteps) { __pipeline_wait_prior(1); }
        else { __pipeline_wait_prior(0); }
        __syncthreads();

        const float* As = sm + (step % STAGES) * A_STG;
        const float* Bs = sm + B_BASE + (step % STAGES) * B_STG;

#pragma unroll
        for (int kk = 0; kk < BK; kk += 8) {
            wmma::fragment<wmma::matrix_a, 16, 16, 8, wmma::precision::tf32,
                           wmma::row_major> afrag[2];
            wmma::fragment<wmma::matrix_b, 16, 16, 8, wmma::precision::tf32,
                           wmma::row_major> bfrag[4];
#pragma unroll
            for (int i = 0; i < 2; ++i)
                wmma::load_matrix_sync(afrag[i], As + (warpM0 + 16 * i) * A_LD + kk, A_LD);
#pragma unroll
            for (int j = 0; j < 4; ++j)
                wmma::load_matrix_sync(bfrag[j], Bs + kk * B_LD + warpN0 + 16 * j, B_LD);
#pragma unroll
            for (int i = 0; i < 2; ++i)
#pragma unroll
                for (int j = 0; j < 4; ++j)
                    wmma::mma_sync(acc[i][j], afrag[i], bfrag[j], acc[i][j]);
        }
        __syncthreads();
    }

    // ---- epilogue: stage tile through smem, fuse extras/identity/rounding ----
#pragma unroll
    for (int i = 0; i < 2; ++i)
#pragma unroll
        for (int j = 0; j < 4; ++j) {
#pragma unroll
            for (int t = 0; t < acc[i][j].num_elements; ++t)
                acc[i][j].x[t] *= alpha;
            wmma::store_matrix_sync(sm + (warpM0 + 16 * i) * EPI_LD + warpN0 + 16 * j,
                                    acc[i][j], EPI_LD, wmma::mem_row_major);
        }
    __syncthreads();

#pragma unroll 4
    for (int s = 0; s < 16; ++s) {
        int f = tid + s * 256;          // float4 id within 128x128 tile
        int r = f >> 5;                 // 32 float4 per row
        int c = (f & 31) << 2;
        float4 v = *reinterpret_cast<const float4*>(sm + r * EPI_LD + c);
        size_t gr = rowBase + r;
        size_t gc = colBase + c;
        size_t gidx = gr * N + gc;
        if (E0) { float4 e = *reinterpret_cast<const float4*>(E0 + gidx);
                  v.x += e0 * e.x; v.y += e0 * e.y; v.z += e0 * e.z; v.w += e0 * e.w; }
        if (E1) { float4 e = *reinterpret_cast<const float4*>(E1 + gidx);
                  v.x += e1 * e.x; v.y += e1 * e.y; v.z += e1 * e.z; v.w += e1 * e.w; }
        if (E2) { float4 e = *reinterpret_cast<const float4*>(E2 + gidx);
                  v.x += e2 * e.x; v.y += e2 * e.y; v.z += e2 * e.z; v.w += e2 * e.w; }
        if (E3) { float4 e = *reinterpret_cast<const float4*>(E3 + gidx);
                  v.x += e3 * e.x; v.y += e3 * e.y; v.z += e3 * e.z; v.w += e3 * e.w; }
        if (idcoef != 0.0f && gr >= gc && gr < gc + 4) {
            if      (gr == gc)     v.x += idcoef;
            else if (gr == gc + 1) v.y += idcoef;
            else if (gr == gc + 2) v.z += idcoef;
            else                   v.w += idcoef;
        }
        if (doRound) {
            v.x = wmma::__float_to_tf32(v.x);
            v.y = wmma::__float_to_tf32(v.y);
            v.z = wmma::__float_to_tf32(v.z);
            v.w = wmma::__float_to_tf32(v.w);
        }
        *reinterpret_cast<float4*>(C + gidx) = v;
    }
}

extern "C" void kernel_launch(void* const* d_in, const int* in_sizes, int n_in,
                              void* d_out, int out_size) {
    const float* X      = (const float*)d_in[0];   // [BATCH, N]
    const float* S_flat = (const float*)d_in[1];   // [N*(N-1)/2]
    float* Y = (float*)d_out;                      // [BATCH, N]

    float *S, *S2, *S3, *S4, *U, *R, *Xr;
    cudaGetSymbolAddress((void**)&S,  g_S);
    cudaGetSymbolAddress((void**)&S2, g_S2);
    cudaGetSymbolAddress((void**)&S3, g_S3);
    cudaGetSymbolAddress((void**)&S4, g_S4);
    cudaGetSymbolAddress((void**)&U,  g_U);
    cudaGetSymbolAddress((void**)&R,  g_R);
    cudaGetSymbolAddress((void**)&Xr, g_X);

    cudaFuncSetAttribute(tf32_gemm_kernel,
                         cudaFuncAttributeMaxDynamicSharedMemorySize, SMEM_BYTES);

    // Taylor coefficients 1/k!
    const float c1 = 1.0f;
    const float c2 = 1.0f / 2.0f;
    const float c3 = 1.0f / 6.0f;
    const float c4 = 1.0f / 24.0f;
    const float c5 = 1.0f / 120.0f;
    const float c6 = 1.0f / 720.0f;
    const float c7 = 1.0f / 5040.0f;
    const float c8 = 1.0f / 40320.0f;
    const float c9 = 1.0f / 362880.0f;

    // 1) S (tf32), Xr = tf32(X)
    build_S_kernel<<<(N_DIM * N_DIM + 255) / 256, 256>>>(S_flat);
    round_X_kernel<<<(BATCH * N_DIM / 4 + 255) / 256, 256>>>(X);

    dim3 gridSq(N_DIM / BN, N_DIM / BM);

    // 2) Powers: S2, S3, S4 (outputs tf32-rounded)
    tf32_gemm_kernel<<<gridSq, 256, SMEM_BYTES>>>(S,  S,  S2, N_DIM, N_DIM, N_DIM,
        1.0f, 0.0f, nullptr,0, nullptr,0, nullptr,0, nullptr,0, 1);
    tf32_gemm_kernel<<<gridSq, 256, SMEM_BYTES>>>(S2, S,  S3, N_DIM, N_DIM, N_DIM,
        1.0f, 0.0f, nullptr,0, nullptr,0, nullptr,0, nullptr,0, 1);
    tf32_gemm_kernel<<<gridSq, 256, SMEM_BYTES>>>(S2, S2, S4, N_DIM, N_DIM, N_DIM,
        1.0f, 0.0f, nullptr,0, nullptr,0, nullptr,0, nullptr,0, 1);

    // 3) Paterson–Stockmeyer:
    // U = c9*(S4@S) + c8*S4 + c7*S3 + c6*S2 + c5*S + c4*I
    tf32_gemm_kernel<<<gridSq, 256, SMEM_BYTES>>>(S4, S, U, N_DIM, N_DIM, N_DIM,
        c9, c4, S4, c8, S3, c7, S2, c6, S, c5, 1);
    // R = (S4@U) + c3*S3 + c2*S2 + c1*S + I
    tf32_gemm_kernel<<<gridSq, 256, SMEM_BYTES>>>(S4, U, R, N_DIM, N_DIM, N_DIM,
        1.0f, 1.0f, S3, c3, S2, c2, S, c1, nullptr, 0, 1);

    // 4) Y = Xr @ R
    dim3 gridY(N_DIM / BN, BATCH / BM);
    tf32_gemm_kernel<<<gridY, 256, SMEM_BYTES>>>(Xr, R, Y, BATCH, N_DIM, N_DIM,
        1.0f, 0.0f, nullptr,0, nullptr,0, nullptr,0, nullptr,0, 0);
}

// round 4
// speedup vs baseline: 9.2737x; 4.2486x over previous
#include <cuda_runtime.h>
#include <cuda_fp16.h>
#include <cuda_pipeline.h>
#include <mma.h>

using namespace nvcuda;

#define N_DIM 2048
#define BATCH 8192

// Scratch (allocation banned -> __device__ globals). All operands fp16.
__device__ __half g_Sh [N_DIM * N_DIM];
__device__ __half g_S2h[N_DIM * N_DIM];
__device__ __half g_S3h[N_DIM * N_DIM];
__device__ __half g_S4h[N_DIM * N_DIM];
__device__ __half g_Uh [N_DIM * N_DIM];
__device__ __half g_Rh [N_DIM * N_DIM];
__device__ __half g_Xh [BATCH * N_DIM];

// Build antisymmetric S (as fp16) from strict-upper-triangle flat vector.
__global__ void build_S_kernel(const float* __restrict__ S_flat) {
    int idx = blockIdx.x * blockDim.x + threadIdx.x;
    if (idx >= N_DIM * N_DIM) return;
    int i = idx / N_DIM;
    int j = idx % N_DIM;
    float v = 0.0f;
    if (i < j) {
        int f = i * (2 * N_DIM - i - 1) / 2 + (j - i - 1);
        v = S_flat[f];
    } else if (i > j) {
        int f = j * (2 * N_DIM - j - 1) / 2 + (i - j - 1);
        v = -S_flat[f];
    }
    g_Sh[idx] = __float2half_rn(v);
}

// Convert X to fp16 once.
__global__ void convert_X_kernel(const float* __restrict__ X) {
    int f = blockIdx.x * blockDim.x + threadIdx.x;   // float4 index (4 elems)
    if (f >= BATCH * N_DIM / 4) return;
    float4 v = reinterpret_cast<const float4*>(X)[f];
    __half2 h0 = __floats2half2_rn(v.x, v.y);
    __half2 h1 = __floats2half2_rn(v.z, v.w);
    uint2 packed;
    packed.x = *reinterpret_cast<unsigned*>(&h0);
    packed.y = *reinterpret_cast<unsigned*>(&h1);
    reinterpret_cast<uint2*>(g_Xh)[f] = packed;
}

// ---------------------------------------------------------------------------
// FP16 wmma GEMM, fp32 accumulate, fused polynomial epilogue:
//   res = alpha*(A@B) + idcoef*I + e0*E0 + e1*E1 + e2*E2 + e3*E3
//   Ch = half(res) (if non-null);  Cf = res (if non-null)
// A: MxK, B: KxN, row-major fp16. M,N multiples of 128; K multiple of 32.
// ---------------------------------------------------------------------------
#define BM 128
#define BN 128
#define BK 32
#define A_LD 40       // 32 + 8 halves pad
#define B_LD 136      // 128 + 8 halves pad
#define STAGES 3
#define A_STG (BM * A_LD)          // 5120 halves
#define B_STG (BK * B_LD)          // 4352 halves
#define B_BASE (STAGES * A_STG)    // in halves
#define EPI_LD 132                 // floats
#define SMEM_BYTES 67584           // max(3*(A_STG+B_STG)*2 = 56832, 128*132*4 = 67584)

__global__ __launch_bounds__(256) void hgemm_kernel(
    const __half* __restrict__ A, const __half* __restrict__ B,
    __half* __restrict__ Ch, float* __restrict__ Cf,
    int M, int N, int K,
    float alpha, float idcoef,
    const __half* __restrict__ E0, float e0,
    const __half* __restrict__ E1, float e1,
    const __half* __restrict__ E2, float e2,
    const __half* __restrict__ E3, float e3)
{
    extern __shared__ char smraw[];
    __half* smh = reinterpret_cast<__half*>(smraw);
    float*  smf = reinterpret_cast<float*>(smraw);

    const int tid = threadIdx.x;
    const int warpId = tid >> 5;
    const int rowBase = blockIdx.y * BM;
    const int colBase = blockIdx.x * BN;

    // warp tile 32(M) x 64(N); warp grid 4x2
    const int warpM0 = (warpId >> 1) * 32;
    const int warpN0 = (warpId & 1) * 64;

    // load mapping (8-half = 16B chunks)
    // A tile: 128x32 halves -> 512 chunks; thread does chunk tid, tid+256
    const int aRow0 = tid >> 2,           aCol0 = (tid & 3) << 3;
    const int aRow1 = (tid + 256) >> 2,   aCol1 = aCol0;
    // B tile: 32x128 halves -> 512 chunks
    const int bRow0 = tid >> 4,           bCol0 = (tid & 15) << 3;
    const int bRow1 = (tid >> 4) + 16,    bCol1 = bCol0;

    const __half* aP0 = A + (size_t)(rowBase + aRow0) * K + aCol0;
    const __half* aP1 = A + (size_t)(rowBase + aRow1) * K + aCol1;
    const __half* bP0 = B + (size_t)bRow0 * N + colBase + bCol0;
    const __half* bP1 = B + (size_t)bRow1 * N + colBase + bCol1;

    const int nsteps = K / BK;

    auto issue = [&](int step) {
        int buf = step % STAGES;
        size_t ka = (size_t)step * BK;
        __half* As = smh + buf * A_STG;
        __half* Bs = smh + B_BASE + buf * B_STG;
        __pipeline_memcpy_async(As + aRow0 * A_LD + aCol0, aP0 + ka, 16);
        __pipeline_memcpy_async(As + aRow1 * A_LD + aCol1, aP1 + ka, 16);
        __pipeline_memcpy_async(Bs + bRow0 * B_LD + bCol0, bP0 + ka * N, 16);
        __pipeline_memcpy_async(Bs + bRow1 * B_LD + bCol1, bP1 + ka * N, 16);
        __pipeline_commit();
    };

    wmma::fragment<wmma::accumulator, 16, 16, 16, float> acc[2][4];
#pragma unroll
    for (int i = 0; i < 2; ++i)
#pragma unroll
        for (int j = 0; j < 4; ++j)
            wmma::fill_fragment(acc[i][j], 0.0f);

    issue(0);
    issue(1);

    for (int step = 0; step < nsteps; ++step) {
        if (step + 2 < nsteps)      { issue(step + 2); __pipeline_wait_prior(2); }
        else if (step + 1 < nsteps) { __pipeline_wait_prior(1); }
        else                        { __pipeline_wait_prior(0); }
        __syncthreads();

        const __half* As = smh + (step % STAGES) * A_STG;
        const __half* Bs = smh + B_BASE + (step % STAGES) * B_STG;

#pragma unroll
        for (int kk = 0; kk < BK; kk += 16) {
            wmma::fragment<wmma::matrix_a, 16, 16, 16, __half, wmma::row_major> afrag[2];
            wmma::fragment<wmma::matrix_b, 16, 16, 16, __half, wmma::row_major> bfrag[4];
#pragma unroll
            for (int i = 0; i < 2; ++i)
                wmma::load_matrix_sync(afrag[i], As + (warpM0 + 16 * i) * A_LD + kk, A_LD);
#pragma unroll
            for (int j = 0; j < 4; ++j)
                wmma::load_matrix_sync(bfrag[j], Bs + kk * B_LD + warpN0 + 16 * j, B_LD);
#pragma unroll
            for (int i = 0; i < 2; ++i)
#pragma unroll
                for (int j = 0; j < 4; ++j)
                    wmma::mma_sync(acc[i][j], afrag[i], bfrag[j], acc[i][j]);
        }
        __syncthreads();
    }

    // ---- epilogue: stage fp32 tile through smem, fuse extras/identity ----
    __syncthreads();
#pragma unroll
    for (int i = 0; i < 2; ++i)
#pragma unroll
        for (int j = 0; j < 4; ++j) {
#pragma unroll
            for (int t = 0; t < acc[i][j].num_elements; ++t)
                acc[i][j].x[t] *= alpha;
            wmma::store_matrix_sync(smf + (warpM0 + 16 * i) * EPI_LD + warpN0 + 16 * j,
                                    acc[i][j], EPI_LD, wmma::mem_row_major);
        }
    __syncthreads();

#pragma unroll 4
    for (int s = 0; s < 16; ++s) {
        int f = tid + s * 256;          // float4-group id within 128x128 tile
        int r = f >> 5;
        int c = (f & 31) << 2;
        float4 v = *reinterpret_cast<const float4*>(smf + r * EPI_LD + c);
        size_t gr = rowBase + r;
        size_t gc = colBase + c;
        size_t gidx = gr * N + gc;

        auto addE = [&](const __half* E, float e) {
            uint2 p = *reinterpret_cast<const uint2*>(E + gidx);
            __half2 h0 = *reinterpret_cast<__half2*>(&p.x);
            __half2 h1 = *reinterpret_cast<__half2*>(&p.y);
            float2 f0 = __half22float2(h0);
            float2 f1 = __half22float2(h1);
            v.x += e * f0.x; v.y += e * f0.y; v.z += e * f1.x; v.w += e * f1.y;
        };
        if (E0) addE(E0, e0);
        if (E1) addE(E1, e1);
        if (E2) addE(E2, e2);
        if (E3) addE(E3, e3);

        if (idcoef != 0.0f && gr >= gc && gr < gc + 4) {
            if      (gr == gc)     v.x += idcoef;
            else if (gr == gc + 1) v.y += idcoef;
            else if (gr == gc + 2) v.z += idcoef;
            else                   v.w += idcoef;
        }

        if (Ch) {
            __half2 h0 = __floats2half2_rn(v.x, v.y);
            __half2 h1 = __floats2half2_rn(v.z, v.w);
            uint2 p;
            p.x = *reinterpret_cast<unsigned*>(&h0);
            p.y = *reinterpret_cast<unsigned*>(&h1);
            *reinterpret_cast<uint2*>(Ch + gidx) = p;
        }
        if (Cf) *reinterpret_cast<float4*>(Cf + gidx) = v;
    }
}

extern "C" void kernel_launch(void* const* d_in, const int* in_sizes, int n_in,
                              void* d_out, int out_size) {
    const float* X      = (const float*)d_in[0];   // [BATCH, N]
    const float* S_flat = (const float*)d_in[1];   // [N*(N-1)/2]
    float* Y = (float*)d_out;                      // [BATCH, N]

    __half *S, *S2, *S3, *S4, *U, *R, *Xh;
    cudaGetSymbolAddress((void**)&S,  g_Sh);
    cudaGetSymbolAddress((void**)&S2, g_S2h);
    cudaGetSymbolAddress((void**)&S3, g_S3h);
    cudaGetSymbolAddress((void**)&S4, g_S4h);
    cudaGetSymbolAddress((void**)&U,  g_Uh);
    cudaGetSymbolAddress((void**)&R,  g_Rh);
    cudaGetSymbolAddress((void**)&Xh, g_Xh);

    cudaFuncSetAttribute(hgemm_kernel,
                         cudaFuncAttributeMaxDynamicSharedMemorySize, SMEM_BYTES);

    // Taylor coefficients 1/k!
    const float c1 = 1.0f;
    const float c2 = 1.0f / 2.0f;
    const float c3 = 1.0f / 6.0f;
    const float c4 = 1.0f / 24.0f;
    const float c5 = 1.0f / 120.0f;
    const float c6 = 1.0f / 720.0f;
    const float c7 = 1.0f / 5040.0f;
    const float c8 = 1.0f / 40320.0f;
    const float c9 = 1.0f / 362880.0f;

    build_S_kernel<<<(N_DIM * N_DIM + 255) / 256, 256>>>(S_flat);
    convert_X_kernel<<<(BATCH * N_DIM / 4 + 255) / 256, 256>>>(X);

    dim3 gridSq(N_DIM / BN, N_DIM / BM);

    // Powers
    hgemm_kernel<<<gridSq, 256, SMEM_BYTES>>>(S,  S,  S2, nullptr, N_DIM, N_DIM, N_DIM,
        1.0f, 0.0f, nullptr,0, nullptr,0, nullptr,0, nullptr,0);
    hgemm_kernel<<<gridSq, 256, SMEM_BYTES>>>(S2, S,  S3, nullptr, N_DIM, N_DIM, N_DIM,
        1.0f, 0.0f, nullptr,0, nullptr,0, nullptr,0, nullptr,0);
    hgemm_kernel<<<gridSq, 256, SMEM_BYTES>>>(S2, S2, S4, nullptr, N_DIM, N_DIM, N_DIM,
        1.0f, 0.0f, nullptr,0, nullptr,0, nullptr,0, nullptr,0);

    // Paterson–Stockmeyer combine:
    // U = c9*(S4@S) + c8*S4 + c7*S3 + c6*S2 + c5*S + c4*I
    hgemm_kernel<<<gridSq, 256, SMEM_BYTES>>>(S4, S, U, nullptr, N_DIM, N_DIM, N_DIM,
        c9, c4, S4, c8, S3, c7, S2, c6, S, c5);
    // R = (S4@U) + c3*S3 + c2*S2 + c1*S + I
    hgemm_kernel<<<gridSq, 256, SMEM_BYTES>>>(S4, U, R, nullptr, N_DIM, N_DIM, N_DIM,
        1.0f, 1.0f, S3, c3, S2, c2, S, c1, nullptr, 0);

    // Y = X @ R   (fp32 out)
    dim3 gridY(N_DIM / BN, BATCH / BM);
    hgemm_kernel<<<gridY, 256, SMEM_BYTES>>>(Xh, R, nullptr, Y, BATCH, N_DIM, N_DIM,
        1.0f, 0.0f, nullptr,0, nullptr,0, nullptr,0, nullptr,0);
}